// round 14
// baseline (speedup 1.0000x reference)
#include <cuda_runtime.h>
#include <cuda_fp16.h>
#include <math.h>
#include <stdint.h>

#define BB 8
#define TT 2048
#define DD 1024
#define HH 64
#define NROWS (BB*TT)
#define NPAR 4

// fp16 Q/K/V scratch
__device__ __half g_q[NROWS*HH];
__device__ __half g_k[NROWS*HH];
__device__ __half g_v[NROWS*HH];
__device__ __half g_wt[192*DD];    // W^T [n][k], q part pre-scaled

// split-k partials: [par][row][dim], m/l in log2 domain
__device__ float g_po[NPAR*NROWS*HH];
__device__ float g_pm[NPAR*NROWS];
__device__ float g_pl[NPAR*NROWS];

#define QSCALE (0.125f * 1.44269504f)   // 1/sqrt(64) * log2(e)

// ---------------------------------------------------------------------------
// Helpers (base sm_100 ISA: ldmatrix / mma.sync / cp.async)
// ---------------------------------------------------------------------------
__device__ __forceinline__ uint32_t smem_u32(const void* p) {
    uint32_t a;
    asm("{ .reg .u64 t; cvta.to.shared.u64 t, %1; cvt.u32.u64 %0, t; }" : "=r"(a) : "l"(p));
    return a;
}
__device__ __forceinline__ void ldm_x4(uint32_t* r, uint32_t addr) {
    asm volatile("ldmatrix.sync.aligned.m8n8.x4.shared.b16 {%0,%1,%2,%3}, [%4];"
                 : "=r"(r[0]), "=r"(r[1]), "=r"(r[2]), "=r"(r[3]) : "r"(addr));
}
__device__ __forceinline__ void ldm_x4_t(uint32_t* r, uint32_t addr) {
    asm volatile("ldmatrix.sync.aligned.m8n8.x4.trans.shared.b16 {%0,%1,%2,%3}, [%4];"
                 : "=r"(r[0]), "=r"(r[1]), "=r"(r[2]), "=r"(r[3]) : "r"(addr));
}
__device__ __forceinline__ void mma_f16(float* c, const uint32_t* a, uint32_t b0, uint32_t b1) {
    asm volatile("mma.sync.aligned.m16n8k16.row.col.f32.f16.f16.f32 "
        "{%0,%1,%2,%3}, {%4,%5,%6,%7}, {%8,%9}, {%0,%1,%2,%3};"
        : "+f"(c[0]), "+f"(c[1]), "+f"(c[2]), "+f"(c[3])
        : "r"(a[0]), "r"(a[1]), "r"(a[2]), "r"(a[3]), "r"(b0), "r"(b1));
}
__device__ __forceinline__ uint32_t pack_h(float lo, float hi) {
    uint32_t d;
    asm("cvt.rn.f16x2.f32 %0, %1, %2;" : "=r"(d) : "f"(hi), "f"(lo));
    return d;
}
__device__ __forceinline__ float ex2(float x) {
    float y;
    asm("ex2.approx.f32 %0, %1;" : "=f"(y) : "f"(x));
    return y;
}
__device__ __forceinline__ void cp16(uint32_t dst, const void* src) {
    asm volatile("cp.async.cg.shared.global [%0], [%1], 16;"
                 :: "r"(dst), "l"(__cvta_generic_to_global(src)));
}
#define CP_COMMIT() asm volatile("cp.async.commit_group;" ::: "memory")
#define CP_WAIT0()  asm volatile("cp.async.wait_group 0;" ::: "memory")
#define CP_WAIT1()  asm volatile("cp.async.wait_group 1;" ::: "memory")

// ---------------------------------------------------------------------------
// W transpose + fp16 convert (q part pre-scaled). grid (6,32), block (32,8)
// ---------------------------------------------------------------------------
__global__ __launch_bounds__(256) void wprep(const float* __restrict__ Wq,
                                             const float* __restrict__ Wk,
                                             const float* __restrict__ Wv)
{
    __shared__ float tile[32][33];
    const int nb = blockIdx.x * 32, kb = blockIdx.y * 32;
    const int tx = threadIdx.x, ty = threadIdx.y;
    const float* W = (nb < 64) ? Wq : (nb < 128 ? Wk : Wv);
    const int ncol = (nb & 63) + tx;
    #pragma unroll
    for (int i = 0; i < 4; i++)
        tile[ty + 8 * i][tx] = W[(size_t)(kb + ty + 8 * i) * HH + ncol];
    __syncthreads();
    const float s = (nb < 64) ? QSCALE : 1.f;
    #pragma unroll
    for (int i = 0; i < 4; i++) {
        int n = nb + ty + 8 * i, k = kb + tx;
        g_wt[(size_t)n * DD + k] = __float2half_rn(tile[tx][ty + 8 * i] * s);
    }
}

// ---------------------------------------------------------------------------
// QKV projection (Round-7 structure, verbatim; at MMA-issue floor ~27us).
// ---------------------------------------------------------------------------
#define PJ_XR(s) ((s) * 32768)
#define PJ_B(s)  (65536 + (s) * 24576)
#define PJ_A 114688
#define PROJ_SMEM 131072

__device__ __forceinline__ void proj_issue_stage(uint32_t sb, int st, int c,
    const float* __restrict__ x, int rowbase)
{
    const int tid = threadIdx.x;
    const int k0 = c * 64;
    #pragma unroll
    for (int i = 0; i < 8; i++) {
        int idx = tid + i * 256;
        int row = idx >> 4, cc = idx & 15;
        cp16(sb + PJ_XR(st) + row * 256 + cc * 16,
             x + (size_t)(rowbase + row) * DD + k0 + cc * 4);
    }
    #pragma unroll
    for (int i = 0; i < 6; i++) {
        int idx = tid + i * 256;
        int row = idx >> 3, cc = idx & 7;
        cp16(sb + PJ_B(st) + row * 128 + (((cc ^ (row & 7)) << 4)),
             g_wt + (size_t)row * DD + k0 + cc * 8);
    }
    CP_COMMIT();
}

__global__ __launch_bounds__(256) void proj_mma(
    const float* __restrict__ x,
    const float* __restrict__ bq, const float* __restrict__ bk, const float* __restrict__ bv)
{
    extern __shared__ __align__(1024) char smem[];
    const uint32_t sb = smem_u32(smem);
    const int tid = threadIdx.x;
    const int wid = tid >> 5, lane = tid & 31;
    const int warpM = wid >> 1, warpN = wid & 1;
    const int rowbase = blockIdx.x * 128;
    const int l15 = lane & 15, lh = lane >> 4;

    float acc[2][12][4];
    #pragma unroll
    for (int m = 0; m < 2; m++)
        #pragma unroll
        for (int n = 0; n < 12; n++)
            #pragma unroll
            for (int e = 0; e < 4; e++) acc[m][n][e] = 0.f;

    proj_issue_stage(sb, 0, 0, x, rowbase);

    for (int c = 0; c < 16; c++) {
        const int st = c & 1;
        if (c + 1 < 16) { proj_issue_stage(sb, st ^ 1, c + 1, x, rowbase); CP_WAIT1(); }
        else CP_WAIT0();
        __syncthreads();

        {
            const int r = tid >> 1, hf = tid & 1;
            const char* xr = smem + PJ_XR(st) + r * 256 + hf * 128;
            #pragma unroll
            for (int j = 0; j < 4; j++) {
                float4 v0 = *(const float4*)(xr + j * 32);
                float4 v1 = *(const float4*)(xr + j * 32 + 16);
                uint32_t h0 = pack_h(v0.x, v0.y), h1 = pack_h(v0.z, v0.w);
                uint32_t h2 = pack_h(v1.x, v1.y), h3 = pack_h(v1.z, v1.w);
                int sw = r * 128 + ((((hf * 4 + j) ^ (r & 7)) << 4));
                *(uint4*)(smem + PJ_A + sw) = make_uint4(h0, h1, h2, h3);
            }
        }
        __syncthreads();

        const uint32_t bbase = sb + PJ_B(st);
        #pragma unroll
        for (int ks = 0; ks < 4; ks++) {
            uint32_t ah[2][4];
            #pragma unroll
            for (int m = 0; m < 2; m++) {
                int row = warpM * 32 + m * 16 + l15;
                ldm_x4(ah[m], sb + PJ_A + row * 128 + ((((ks * 2 + lh) ^ (row & 7)) << 4)));
            }
            #pragma unroll
            for (int np = 0; np < 6; np++) {
                int n = warpN * 96 + np * 16 + l15;
                uint32_t bh[4];
                ldm_x4(bh, bbase + n * 128 + ((((ks * 2 + lh) ^ (n & 7)) << 4)));
                #pragma unroll
                for (int m = 0; m < 2; m++)
                    #pragma unroll
                    for (int sub = 0; sub < 2; sub++)
                        mma_f16(acc[m][np * 2 + sub], ah[m], bh[sub], bh[sub + 2]);
            }
        }
        __syncthreads();
    }

    #pragma unroll
    for (int m = 0; m < 2; m++) {
        int r0 = rowbase + warpM * 32 + m * 16 + (lane >> 2);
        #pragma unroll
        for (int nt = 0; nt < 12; nt++) {
            int g = warpN * 96 + nt * 8 + (lane & 3) * 2;
            __half* dst; const float* bias; int cc; float s;
            if (g < 64)       { dst = g_q; bias = bq; cc = g;       s = QSCALE; }
            else if (g < 128) { dst = g_k; bias = bk; cc = g - 64;  s = 1.f; }
            else              { dst = g_v; bias = bv; cc = g - 128; s = 1.f; }
            float b0 = bias[cc] * s, b1 = bias[cc + 1] * s;
            uint32_t h0 = pack_h(acc[m][nt][0] + b0, acc[m][nt][1] + b1);
            uint32_t h1 = pack_h(acc[m][nt][2] + b0, acc[m][nt][3] + b1);
            *(uint32_t*)((char*)dst + ((size_t)r0 * 64 + cc) * 2) = h0;
            *(uint32_t*)((char*)dst + ((size_t)(r0 + 8) * 64 + cc) * 2) = h1;
        }
    }
}

// ---------------------------------------------------------------------------
// Flash attention, 4-way split-k partials.
// grid (32, 8) = 256 CTAs -> 2 co-resident CTAs/SM (independent phases).
// CTA (pr, par, b): qtiles pr and 15-pr, k-units kt == par (mod 4).
// 256 threads / 8 warps, 16 q-rows per warp. QT=128, KT=64.
// ---------------------------------------------------------------------------
#define FQ 0
#define FST(s) (16384 + (s) * 16384)   // K 8K | V 8K
#define FLASH_SMEM (16384 + 2*16384)   // 49152

__device__ __forceinline__ void flash_issue_q(uint32_t sb, int qbase, size_t hb)
{
    const int tid = threadIdx.x;
    #pragma unroll
    for (int i = 0; i < 4; i++) {
        int idx = tid + i * 256;
        int row = idx >> 3, cc = idx & 7;
        cp16(sb + FQ + row * 128 + (((cc ^ (row & 7)) << 4)),
             g_q + hb + (size_t)(qbase + row) * 64 + cc * 8);
    }
}

__device__ __forceinline__ void flash_issue_stage(uint32_t sb, int st, int kbase, size_t hb)
{
    const int tid = threadIdx.x;
    const uint32_t stb = sb + FST(st);
    #pragma unroll
    for (int i = 0; i < 4; i++) {
        int idx = tid + i * 256;
        int arr = idx >> 9, rem = idx & 511;
        int row = rem >> 3, cc = rem & 7;
        const __half* base = arr ? g_v : g_k;
        cp16(stb + arr * 8192 + row * 128 + (((cc ^ (row & 7)) << 4)),
             base + hb + (size_t)(kbase + row) * 64 + cc * 8);
    }
    CP_COMMIT();
}

__global__ __launch_bounds__(256) void flash(void)
{
    extern __shared__ __align__(1024) char smem[];
    const uint32_t sb = smem_u32(smem);
    const int tid = threadIdx.x;
    const int wid = tid >> 5, lane = tid & 31;
    const int l15 = lane & 15, lh = lane >> 4;
    const int pr  = blockIdx.x >> 2;   // 0..7
    const int par = blockIdx.x & 3;    // 0..3
    const int b   = blockIdx.y;
    const size_t hb = (size_t)b * TT * HH;

    #pragma unroll 1
    for (int half = 0; half < 2; half++) {
        const int qtile = half ? (15 - pr) : pr;
        const int qbase = qtile * 128;
        const int ktmax = 2 * qtile + 1;
        const int nunits = (par <= ktmax) ? (((ktmax - par) >> 2) + 1) : 0;

        flash_issue_q(sb, qbase, hb);
        flash_issue_stage(sb, 0, par * 64, hb);

        float O[8][4];
        float m0 = -1e30f, m1 = -1e30f, l0 = 0.f, l1 = 0.f;
        #pragma unroll
        for (int n = 0; n < 8; n++)
            #pragma unroll
            for (int e = 0; e < 4; e++) O[n][e] = 0.f;

        for (int u = 0; u < nunits; u++) {
            const int kt = par + 4 * u;
            const uint32_t stb = sb + FST(u & 1);
            if (u + 1 < nunits) { flash_issue_stage(sb, (u + 1) & 1, (par + 4 * (u + 1)) * 64, hb); CP_WAIT1(); }
            else CP_WAIT0();
            __syncthreads();

            // ---- S = Q K^T : 16 rows x 64 cols per warp ----
            float S[8][4];
            #pragma unroll
            for (int n = 0; n < 8; n++)
                #pragma unroll
                for (int e = 0; e < 4; e++) S[n][e] = 0.f;

            #pragma unroll
            for (int ks = 0; ks < 4; ks++) {
                uint32_t qh[4];
                {
                    int row = wid * 16 + l15;
                    ldm_x4(qh, sb + FQ + row * 128 + ((((ks * 2 + lh) ^ (row & 7)) << 4)));
                }
                #pragma unroll
                for (int np = 0; np < 4; np++) {
                    int n = np * 16 + l15;
                    uint32_t kh[4];
                    ldm_x4(kh, stb + n * 128 + ((((ks * 2 + lh) ^ (n & 7)) << 4)));
                    #pragma unroll
                    for (int sub = 0; sub < 2; sub++)
                        mma_f16(S[np * 2 + sub], qh, kh[sub], kh[sub + 2]);
                }
            }

            // ---- causal mask (only the last unit can touch the diagonal) ----
            if (u == nunits - 1 && kt >= 2 * qtile) {
                const int cb = kt * 64 + (lane & 3) * 2;
                int r0 = qbase + wid * 16 + (lane >> 2);
                #pragma unroll
                for (int j = 0; j < 8; j++) {
                    int kc = cb + j * 8;
                    if (kc     > r0)     S[j][0] = -1e30f;
                    if (kc + 1 > r0)     S[j][1] = -1e30f;
                    if (kc     > r0 + 8) S[j][2] = -1e30f;
                    if (kc + 1 > r0 + 8) S[j][3] = -1e30f;
                }
            }

            // ---- online softmax (log2 domain, MUFU ex2) ----
            {
                float mx0 = -1e30f, mx1 = -1e30f;
                #pragma unroll
                for (int j = 0; j < 8; j++) {
                    mx0 = fmaxf(mx0, fmaxf(S[j][0], S[j][1]));
                    mx1 = fmaxf(mx1, fmaxf(S[j][2], S[j][3]));
                }
                mx0 = fmaxf(mx0, __shfl_xor_sync(0xffffffffu, mx0, 1));
                mx0 = fmaxf(mx0, __shfl_xor_sync(0xffffffffu, mx0, 2));
                mx1 = fmaxf(mx1, __shfl_xor_sync(0xffffffffu, mx1, 1));
                mx1 = fmaxf(mx1, __shfl_xor_sync(0xffffffffu, mx1, 2));
                float mn0 = fmaxf(m0, mx0), mn1 = fmaxf(m1, mx1);
                float a0 = ex2(m0 - mn0), a1 = ex2(m1 - mn1);
                float s0 = 0.f, s1 = 0.f;
                #pragma unroll
                for (int j = 0; j < 8; j++) {
                    S[j][0] = ex2(S[j][0] - mn0); s0 += S[j][0];
                    S[j][1] = ex2(S[j][1] - mn0); s0 += S[j][1];
                    S[j][2] = ex2(S[j][2] - mn1); s1 += S[j][2];
                    S[j][3] = ex2(S[j][3] - mn1); s1 += S[j][3];
                }
                s0 += __shfl_xor_sync(0xffffffffu, s0, 1);
                s0 += __shfl_xor_sync(0xffffffffu, s0, 2);
                s1 += __shfl_xor_sync(0xffffffffu, s1, 1);
                s1 += __shfl_xor_sync(0xffffffffu, s1, 2);
                l0 = l0 * a0 + s0; l1 = l1 * a1 + s1;
                m0 = mn0; m1 = mn1;
                #pragma unroll
                for (int j = 0; j < 8; j++) {
                    O[j][0] *= a0; O[j][1] *= a0;
                    O[j][2] *= a1; O[j][3] *= a1;
                }
            }

            // ---- O += P V ----
            #pragma unroll
            for (int ks2 = 0; ks2 < 4; ks2++) {
                const int j0 = 2 * ks2, j1 = j0 + 1;
                uint32_t ph[4];
                ph[0] = pack_h(S[j0][0], S[j0][1]);
                ph[1] = pack_h(S[j0][2], S[j0][3]);
                ph[2] = pack_h(S[j1][0], S[j1][1]);
                ph[3] = pack_h(S[j1][2], S[j1][3]);
                #pragma unroll
                for (int dp = 0; dp < 4; dp++) {
                    int krow = ks2 * 16 + l15;
                    uint32_t vh[4];
                    ldm_x4_t(vh, stb + 8192 + krow * 128 + ((((dp * 2 + lh) ^ (krow & 7)) << 4)));
                    mma_f16(O[dp * 2],     ph, vh[0], vh[1]);
                    mma_f16(O[dp * 2 + 1], ph, vh[2], vh[3]);
                }
            }
            __syncthreads();
        }

        if (nunits == 0) {   // drain outstanding cp.async before smem reuse
            CP_WAIT0();
            __syncthreads();
        }

        // ---- write unnormalized partials ----
        {
            int rl = qbase + wid * 16 + (lane >> 2);
            size_t row0 = (size_t)par * NROWS + b * TT + rl;
            #pragma unroll
            for (int j = 0; j < 8; j++) {
                int dc = j * 8 + (lane & 3) * 2;
                *(float2*)(g_po + row0 * 64 + dc)       = make_float2(O[j][0], O[j][1]);
                *(float2*)(g_po + (row0 + 8) * 64 + dc) = make_float2(O[j][2], O[j][3]);
            }
            if ((lane & 3) == 0) {
                g_pm[row0] = m0;     g_pm[row0 + 8] = m1;
                g_pl[row0] = l0;     g_pl[row0 + 8] = l1;
            }
        }
    }
}

// ---------------------------------------------------------------------------
// Combine 4 parity partials. grid 1024, block 256; 16 threads/row.
// ---------------------------------------------------------------------------
__global__ __launch_bounds__(256) void combine(float* __restrict__ out)
{
    int idx = blockIdx.x * 256 + threadIdx.x;     // < 16384*16
    int row = idx >> 4, c4 = idx & 15;
    float m[NPAR], l[NPAR];
    #pragma unroll
    for (int p = 0; p < NPAR; p++) {
        m[p] = g_pm[(size_t)p * NROWS + row];
        l[p] = g_pl[(size_t)p * NROWS + row];
    }
    float mx = fmaxf(fmaxf(m[0], m[1]), fmaxf(m[2], m[3]));
    float w[NPAR], den = 0.f;
    #pragma unroll
    for (int p = 0; p < NPAR; p++) { w[p] = ex2(m[p] - mx); den += l[p] * w[p]; }
    float inv = 1.f / den;
    float4 acc = make_float4(0.f, 0.f, 0.f, 0.f);
    #pragma unroll
    for (int p = 0; p < NPAR; p++) {
        float4 a = *(const float4*)(g_po + ((size_t)p * NROWS + row) * 64 + c4 * 4);
        acc.x += a.x * w[p]; acc.y += a.y * w[p];
        acc.z += a.z * w[p]; acc.w += a.w * w[p];
    }
    acc.x *= inv; acc.y *= inv; acc.z *= inv; acc.w *= inv;
    *(float4*)(out + (size_t)row * 64 + c4 * 4) = acc;
}

extern "C" void kernel_launch(void* const* d_in, const int* in_sizes, int n_in,
                              void* d_out, int out_size)
{
    const float* x  = (const float*)d_in[0];
    const float* Wq = (const float*)d_in[1];
    const float* bq = (const float*)d_in[2];
    const float* Wk = (const float*)d_in[3];
    const float* bk = (const float*)d_in[4];
    const float* Wv = (const float*)d_in[5];
    const float* bv = (const float*)d_in[6];
    float* out = (float*)d_out;

    dim3 wg(6, 32), wb(32, 8);
    wprep<<<wg, wb>>>(Wq, Wk, Wv);

    cudaFuncSetAttribute(proj_mma, cudaFuncAttributeMaxDynamicSharedMemorySize, PROJ_SMEM);
    proj_mma<<<NROWS / 128, 256, PROJ_SMEM>>>(x, bq, bk, bv);

    cudaFuncSetAttribute(flash, cudaFuncAttributeMaxDynamicSharedMemorySize, FLASH_SMEM);
    dim3 g(32, BB);   // 8 pairs x 4 parity x 8 batches = 256 CTAs
    flash<<<g, 256, FLASH_SMEM>>>();

    combine<<<NROWS * 16 / 256, 256>>>(out);
}

// round 15
// speedup vs baseline: 1.0697x; 1.0697x over previous
#include <cuda_runtime.h>
#include <cuda_fp16.h>
#include <math.h>
#include <stdint.h>

#define BB 8
#define TT 2048
#define DD 1024
#define HH 64
#define NROWS (BB*TT)
#define NPAR 2

// fp16 Q/K/V scratch
__device__ __half g_q[NROWS*HH];
__device__ __half g_k[NROWS*HH];
__device__ __half g_v[NROWS*HH];
__device__ __half g_wt[192*DD];    // W^T [n][k], q part pre-scaled

// split-k partials: [par][row][dim], m/l in log2 domain
__device__ float g_po[NPAR*NROWS*HH];
__device__ float g_pm[NPAR*NROWS];
__device__ float g_pl[NPAR*NROWS];

#define QSCALE (0.125f * 1.44269504f)   // 1/sqrt(64) * log2(e)

// ---------------------------------------------------------------------------
// Helpers (base sm_100 ISA: ldmatrix / mma.sync / cp.async)
// ---------------------------------------------------------------------------
__device__ __forceinline__ uint32_t smem_u32(const void* p) {
    uint32_t a;
    asm("{ .reg .u64 t; cvta.to.shared.u64 t, %1; cvt.u32.u64 %0, t; }" : "=r"(a) : "l"(p));
    return a;
}
__device__ __forceinline__ void ldm_x4(uint32_t* r, uint32_t addr) {
    asm volatile("ldmatrix.sync.aligned.m8n8.x4.shared.b16 {%0,%1,%2,%3}, [%4];"
                 : "=r"(r[0]), "=r"(r[1]), "=r"(r[2]), "=r"(r[3]) : "r"(addr));
}
__device__ __forceinline__ void ldm_x4_t(uint32_t* r, uint32_t addr) {
    asm volatile("ldmatrix.sync.aligned.m8n8.x4.trans.shared.b16 {%0,%1,%2,%3}, [%4];"
                 : "=r"(r[0]), "=r"(r[1]), "=r"(r[2]), "=r"(r[3]) : "r"(addr));
}
__device__ __forceinline__ void mma_f16(float* c, const uint32_t* a, uint32_t b0, uint32_t b1) {
    asm volatile("mma.sync.aligned.m16n8k16.row.col.f32.f16.f16.f32 "
        "{%0,%1,%2,%3}, {%4,%5,%6,%7}, {%8,%9}, {%0,%1,%2,%3};"
        : "+f"(c[0]), "+f"(c[1]), "+f"(c[2]), "+f"(c[3])
        : "r"(a[0]), "r"(a[1]), "r"(a[2]), "r"(a[3]), "r"(b0), "r"(b1));
}
__device__ __forceinline__ uint32_t pack_h(float lo, float hi) {
    uint32_t d;
    asm("cvt.rn.f16x2.f32 %0, %1, %2;" : "=r"(d) : "f"(hi), "f"(lo));
    return d;
}
__device__ __forceinline__ float ex2(float x) {
    float y;
    asm("ex2.approx.f32 %0, %1;" : "=f"(y) : "f"(x));
    return y;
}
__device__ __forceinline__ void cp16(uint32_t dst, const void* src) {
    asm volatile("cp.async.cg.shared.global [%0], [%1], 16;"
                 :: "r"(dst), "l"(__cvta_generic_to_global(src)));
}
#define CP_COMMIT() asm volatile("cp.async.commit_group;" ::: "memory")
#define CP_WAIT0()  asm volatile("cp.async.wait_group 0;" ::: "memory")
#define CP_WAIT1()  asm volatile("cp.async.wait_group 1;" ::: "memory")

// ---------------------------------------------------------------------------
// W transpose + fp16 convert (q part pre-scaled). grid (6,32), block (32,8)
// ---------------------------------------------------------------------------
__global__ __launch_bounds__(256) void wprep(const float* __restrict__ Wq,
                                             const float* __restrict__ Wk,
                                             const float* __restrict__ Wv)
{
    __shared__ float tile[32][33];
    const int nb = blockIdx.x * 32, kb = blockIdx.y * 32;
    const int tx = threadIdx.x, ty = threadIdx.y;
    const float* W = (nb < 64) ? Wq : (nb < 128 ? Wk : Wv);
    const int ncol = (nb & 63) + tx;
    #pragma unroll
    for (int i = 0; i < 4; i++)
        tile[ty + 8 * i][tx] = W[(size_t)(kb + ty + 8 * i) * HH + ncol];
    __syncthreads();
    const float s = (nb < 64) ? QSCALE : 1.f;
    #pragma unroll
    for (int i = 0; i < 4; i++) {
        int n = nb + ty + 8 * i, k = kb + tx;
        g_wt[(size_t)n * DD + k] = __float2half_rn(tile[tx][ty + 8 * i] * s);
    }
}

// ---------------------------------------------------------------------------
// QKV projection (Round-7 structure, verbatim; at MMA-issue floor ~27us).
// ---------------------------------------------------------------------------
#define PJ_XR(s) ((s) * 32768)
#define PJ_B(s)  (65536 + (s) * 24576)
#define PJ_A 114688
#define PROJ_SMEM 131072

__device__ __forceinline__ void proj_issue_stage(uint32_t sb, int st, int c,
    const float* __restrict__ x, int rowbase)
{
    const int tid = threadIdx.x;
    const int k0 = c * 64;
    #pragma unroll
    for (int i = 0; i < 8; i++) {
        int idx = tid + i * 256;
        int row = idx >> 4, cc = idx & 15;
        cp16(sb + PJ_XR(st) + row * 256 + cc * 16,
             x + (size_t)(rowbase + row) * DD + k0 + cc * 4);
    }
    #pragma unroll
    for (int i = 0; i < 6; i++) {
        int idx = tid + i * 256;
        int row = idx >> 3, cc = idx & 7;
        cp16(sb + PJ_B(st) + row * 128 + (((cc ^ (row & 7)) << 4)),
             g_wt + (size_t)row * DD + k0 + cc * 8);
    }
    CP_COMMIT();
}

__global__ __launch_bounds__(256) void proj_mma(
    const float* __restrict__ x,
    const float* __restrict__ bq, const float* __restrict__ bk, const float* __restrict__ bv)
{
    extern __shared__ __align__(1024) char smem[];
    const uint32_t sb = smem_u32(smem);
    const int tid = threadIdx.x;
    const int wid = tid >> 5, lane = tid & 31;
    const int warpM = wid >> 1, warpN = wid & 1;
    const int rowbase = blockIdx.x * 128;
    const int l15 = lane & 15, lh = lane >> 4;

    float acc[2][12][4];
    #pragma unroll
    for (int m = 0; m < 2; m++)
        #pragma unroll
        for (int n = 0; n < 12; n++)
            #pragma unroll
            for (int e = 0; e < 4; e++) acc[m][n][e] = 0.f;

    proj_issue_stage(sb, 0, 0, x, rowbase);

    for (int c = 0; c < 16; c++) {
        const int st = c & 1;
        if (c + 1 < 16) { proj_issue_stage(sb, st ^ 1, c + 1, x, rowbase); CP_WAIT1(); }
        else CP_WAIT0();
        __syncthreads();

        {
            const int r = tid >> 1, hf = tid & 1;
            const char* xr = smem + PJ_XR(st) + r * 256 + hf * 128;
            #pragma unroll
            for (int j = 0; j < 4; j++) {
                float4 v0 = *(const float4*)(xr + j * 32);
                float4 v1 = *(const float4*)(xr + j * 32 + 16);
                uint32_t h0 = pack_h(v0.x, v0.y), h1 = pack_h(v0.z, v0.w);
                uint32_t h2 = pack_h(v1.x, v1.y), h3 = pack_h(v1.z, v1.w);
                int sw = r * 128 + ((((hf * 4 + j) ^ (r & 7)) << 4));
                *(uint4*)(smem + PJ_A + sw) = make_uint4(h0, h1, h2, h3);
            }
        }
        __syncthreads();

        const uint32_t bbase = sb + PJ_B(st);
        #pragma unroll
        for (int ks = 0; ks < 4; ks++) {
            uint32_t ah[2][4];
            #pragma unroll
            for (int m = 0; m < 2; m++) {
                int row = warpM * 32 + m * 16 + l15;
                ldm_x4(ah[m], sb + PJ_A + row * 128 + ((((ks * 2 + lh) ^ (row & 7)) << 4)));
            }
            #pragma unroll
            for (int np = 0; np < 6; np++) {
                int n = warpN * 96 + np * 16 + l15;
                uint32_t bh[4];
                ldm_x4(bh, bbase + n * 128 + ((((ks * 2 + lh) ^ (n & 7)) << 4)));
                #pragma unroll
                for (int m = 0; m < 2; m++)
                    #pragma unroll
                    for (int sub = 0; sub < 2; sub++)
                        mma_f16(acc[m][np * 2 + sub], ah[m], bh[sub], bh[sub + 2]);
            }
        }
        __syncthreads();
    }

    #pragma unroll
    for (int m = 0; m < 2; m++) {
        int r0 = rowbase + warpM * 32 + m * 16 + (lane >> 2);
        #pragma unroll
        for (int nt = 0; nt < 12; nt++) {
            int g = warpN * 96 + nt * 8 + (lane & 3) * 2;
            __half* dst; const float* bias; int cc; float s;
            if (g < 64)       { dst = g_q; bias = bq; cc = g;       s = QSCALE; }
            else if (g < 128) { dst = g_k; bias = bk; cc = g - 64;  s = 1.f; }
            else              { dst = g_v; bias = bv; cc = g - 128; s = 1.f; }
            float b0 = bias[cc] * s, b1 = bias[cc + 1] * s;
            uint32_t h0 = pack_h(acc[m][nt][0] + b0, acc[m][nt][1] + b1);
            uint32_t h1 = pack_h(acc[m][nt][2] + b0, acc[m][nt][3] + b1);
            *(uint32_t*)((char*)dst + ((size_t)r0 * 64 + cc) * 2) = h0;
            *(uint32_t*)((char*)dst + ((size_t)(r0 + 8) * 64 + cc) * 2) = h1;
        }
    }
}

// ---------------------------------------------------------------------------
// Flash attention, KT=128 per iteration (half the softmax/barrier phases).
// 128 CTAs (1/SM): grid (16, 8) = (8 pairs x 2 parity, batch).
// CTA (pr, par, b): qtiles pr and 15-pr, KT-128 units kt == par (mod 2).
// 256 threads / 8 warps, 16 q-rows per warp. QT=128.
// ---------------------------------------------------------------------------
#define FQ 0
#define FST(s) (16384 + (s) * 32768)   // K 16K | V 16K
#define FLASH_SMEM (16384 + 2*32768)   // 81920

__device__ __forceinline__ void flash_issue_q(uint32_t sb, int qbase, size_t hb)
{
    const int tid = threadIdx.x;
    #pragma unroll
    for (int i = 0; i < 4; i++) {
        int idx = tid + i * 256;                  // < 1024 (128 rows x 8)
        int row = idx >> 3, cc = idx & 7;
        cp16(sb + FQ + row * 128 + (((cc ^ (row & 7)) << 4)),
             g_q + hb + (size_t)(qbase + row) * 64 + cc * 8);
    }
}

__device__ __forceinline__ void flash_issue_stage(uint32_t sb, int st, int kbase, size_t hb)
{
    const int tid = threadIdx.x;
    const uint32_t stb = sb + FST(st);
    #pragma unroll
    for (int i = 0; i < 8; i++) {
        int idx = tid + i * 256;                  // < 2048 (2 arrays x 128 rows x 8)
        int arr = idx >> 10, rem = idx & 1023;
        int row = rem >> 3, cc = rem & 7;
        const __half* base = arr ? g_v : g_k;
        cp16(stb + arr * 16384 + row * 128 + (((cc ^ (row & 7)) << 4)),
             base + hb + (size_t)(kbase + row) * 64 + cc * 8);
    }
    CP_COMMIT();
}

__global__ __launch_bounds__(256) void flash(void)
{
    extern __shared__ __align__(1024) char smem[];
    const uint32_t sb = smem_u32(smem);
    const int tid = threadIdx.x;
    const int wid = tid >> 5, lane = tid & 31;
    const int l15 = lane & 15, lh = lane >> 4;
    const int pr  = blockIdx.x >> 1;   // 0..7
    const int par = blockIdx.x & 1;    // 0..1
    const int b   = blockIdx.y;
    const size_t hb = (size_t)b * TT * HH;

    #pragma unroll 1
    for (int half = 0; half < 2; half++) {
        const int qtile = half ? (15 - pr) : pr;
        const int qbase = qtile * 128;
        const int nunits = (par <= qtile) ? (((qtile - par) >> 1) + 1) : 0;

        flash_issue_q(sb, qbase, hb);
        flash_issue_stage(sb, 0, par * 128, hb);

        float O[8][4];
        float m0 = -1e30f, m1 = -1e30f, l0 = 0.f, l1 = 0.f;
        #pragma unroll
        for (int n = 0; n < 8; n++)
            #pragma unroll
            for (int e = 0; e < 4; e++) O[n][e] = 0.f;

        for (int u = 0; u < nunits; u++) {
            const int kt = par + 2 * u;
            const uint32_t stb = sb + FST(u & 1);
            if (u + 1 < nunits) { flash_issue_stage(sb, (u + 1) & 1, (par + 2 * (u + 1)) * 128, hb); CP_WAIT1(); }
            else CP_WAIT0();
            __syncthreads();

            // ---- S = Q K^T : 16 rows x 128 cols per warp ----
            float S[16][4];
            #pragma unroll
            for (int n = 0; n < 16; n++)
                #pragma unroll
                for (int e = 0; e < 4; e++) S[n][e] = 0.f;

            #pragma unroll
            for (int ks = 0; ks < 4; ks++) {
                uint32_t qh[4];
                {
                    int row = wid * 16 + l15;
                    ldm_x4(qh, sb + FQ + row * 128 + ((((ks * 2 + lh) ^ (row & 7)) << 4)));
                }
                #pragma unroll
                for (int np = 0; np < 8; np++) {
                    int n = np * 16 + l15;
                    uint32_t kh[4];
                    ldm_x4(kh, stb + n * 128 + ((((ks * 2 + lh) ^ (n & 7)) << 4)));
                    #pragma unroll
                    for (int sub = 0; sub < 2; sub++)
                        mma_f16(S[np * 2 + sub], qh, kh[sub], kh[sub + 2]);
                }
            }

            // ---- causal mask (diagonal unit only: QT==KT -> local compare) ----
            if (kt == qtile) {
                const int cb = (lane & 3) * 2;
                const int rl = wid * 16 + (lane >> 2);
                #pragma unroll
                for (int j = 0; j < 16; j++) {
                    int kc = cb + j * 8;
                    if (kc     > rl)     S[j][0] = -1e30f;
                    if (kc + 1 > rl)     S[j][1] = -1e30f;
                    if (kc     > rl + 8) S[j][2] = -1e30f;
                    if (kc + 1 > rl + 8) S[j][3] = -1e30f;
                }
            }

            // ---- online softmax (log2 domain, MUFU ex2) ----
            {
                float mx0 = -1e30f, mx1 = -1e30f;
                #pragma unroll
                for (int j = 0; j < 16; j++) {
                    mx0 = fmaxf(mx0, fmaxf(S[j][0], S[j][1]));
                    mx1 = fmaxf(mx1, fmaxf(S[j][2], S[j][3]));
                }
                mx0 = fmaxf(mx0, __shfl_xor_sync(0xffffffffu, mx0, 1));
                mx0 = fmaxf(mx0, __shfl_xor_sync(0xffffffffu, mx0, 2));
                mx1 = fmaxf(mx1, __shfl_xor_sync(0xffffffffu, mx1, 1));
                mx1 = fmaxf(mx1, __shfl_xor_sync(0xffffffffu, mx1, 2));
                float mn0 = fmaxf(m0, mx0), mn1 = fmaxf(m1, mx1);
                float a0 = ex2(m0 - mn0), a1 = ex2(m1 - mn1);
                float s0 = 0.f, s1 = 0.f;
                #pragma unroll
                for (int j = 0; j < 16; j++) {
                    S[j][0] = ex2(S[j][0] - mn0); s0 += S[j][0];
                    S[j][1] = ex2(S[j][1] - mn0); s0 += S[j][1];
                    S[j][2] = ex2(S[j][2] - mn1); s1 += S[j][2];
                    S[j][3] = ex2(S[j][3] - mn1); s1 += S[j][3];
                }
                s0 += __shfl_xor_sync(0xffffffffu, s0, 1);
                s0 += __shfl_xor_sync(0xffffffffu, s0, 2);
                s1 += __shfl_xor_sync(0xffffffffu, s1, 1);
                s1 += __shfl_xor_sync(0xffffffffu, s1, 2);
                l0 = l0 * a0 + s0; l1 = l1 * a1 + s1;
                m0 = mn0; m1 = mn1;
                #pragma unroll
                for (int j = 0; j < 8; j++) {
                    O[j][0] *= a0; O[j][1] *= a0;
                    O[j][2] *= a1; O[j][3] *= a1;
                }
            }

            // ---- O += P V (K-dim = 128) ----
            #pragma unroll
            for (int ks2 = 0; ks2 < 8; ks2++) {
                const int j0 = 2 * ks2, j1 = j0 + 1;
                uint32_t ph[4];
                ph[0] = pack_h(S[j0][0], S[j0][1]);
                ph[1] = pack_h(S[j0][2], S[j0][3]);
                ph[2] = pack_h(S[j1][0], S[j1][1]);
                ph[3] = pack_h(S[j1][2], S[j1][3]);
                #pragma unroll
                for (int dp = 0; dp < 4; dp++) {
                    int krow = ks2 * 16 + l15;
                    uint32_t vh[4];
                    ldm_x4_t(vh, stb + 16384 + krow * 128 + ((((dp * 2 + lh) ^ (krow & 7)) << 4)));
                    mma_f16(O[dp * 2],     ph, vh[0], vh[1]);
                    mma_f16(O[dp * 2 + 1], ph, vh[2], vh[3]);
                }
            }
            __syncthreads();
        }

        if (nunits == 0) {   // drain outstanding cp.async before smem reuse
            CP_WAIT0();
            __syncthreads();
        }

        // ---- write unnormalized partials ----
        {
            int rl = qbase + wid * 16 + (lane >> 2);
            size_t row0 = (size_t)par * NROWS + b * TT + rl;
            #pragma unroll
            for (int j = 0; j < 8; j++) {
                int dc = j * 8 + (lane & 3) * 2;
                *(float2*)(g_po + row0 * 64 + dc)       = make_float2(O[j][0], O[j][1]);
                *(float2*)(g_po + (row0 + 8) * 64 + dc) = make_float2(O[j][2], O[j][3]);
            }
            if ((lane & 3) == 0) {
                g_pm[row0] = m0;     g_pm[row0 + 8] = m1;
                g_pl[row0] = l0;     g_pl[row0 + 8] = l1;
            }
        }
    }
}

// ---------------------------------------------------------------------------
// Combine 2 parity partials (R13 form). grid 1024, block 256.
// ---------------------------------------------------------------------------
__global__ __launch_bounds__(256) void combine(float* __restrict__ out)
{
    int idx = blockIdx.x * 256 + threadIdx.x;     // < 16384*16
    int row = idx >> 4, c4 = idx & 15;
    float m0 = g_pm[row], m1 = g_pm[NROWS + row];
    float l0 = g_pl[row], l1 = g_pl[NROWS + row];
    float mx = fmaxf(m0, m1);
    float w0 = ex2(m0 - mx), w1 = ex2(m1 - mx);
    float inv = 1.f / (l0 * w0 + l1 * w1);
    float4 a = *(const float4*)(g_po + (size_t)row * 64 + c4 * 4);
    float4 c = *(const float4*)(g_po + ((size_t)NROWS + row) * 64 + c4 * 4);
    float4 o;
    o.x = (a.x * w0 + c.x * w1) * inv;
    o.y = (a.y * w0 + c.y * w1) * inv;
    o.z = (a.z * w0 + c.z * w1) * inv;
    o.w = (a.w * w0 + c.w * w1) * inv;
    *(float4*)(out + (size_t)row * 64 + c4 * 4) = o;
}

extern "C" void kernel_launch(void* const* d_in, const int* in_sizes, int n_in,
                              void* d_out, int out_size)
{
    const float* x  = (const float*)d_in[0];
    const float* Wq = (const float*)d_in[1];
    const float* bq = (const float*)d_in[2];
    const float* Wk = (const float*)d_in[3];
    const float* bk = (const float*)d_in[4];
    const float* Wv = (const float*)d_in[5];
    const float* bv = (const float*)d_in[6];
    float* out = (float*)d_out;

    dim3 wg(6, 32), wb(32, 8);
    wprep<<<wg, wb>>>(Wq, Wk, Wv);

    cudaFuncSetAttribute(proj_mma, cudaFuncAttributeMaxDynamicSharedMemorySize, PROJ_SMEM);
    proj_mma<<<NROWS / 128, 256, PROJ_SMEM>>>(x, bq, bk, bv);

    cudaFuncSetAttribute(flash, cudaFuncAttributeMaxDynamicSharedMemorySize, FLASH_SMEM);
    dim3 g(16, BB);   // 8 pairs x 2 parity x 8 batches = 128 CTAs
    flash<<<g, 256, FLASH_SMEM>>>();

    combine<<<NROWS * 16 / 256, 256>>>(out);
}